// round 12
// baseline (speedup 1.0000x reference)
#include <cuda_runtime.h>
#include <cuda_fp16.h>
#include <cstdint>

// ---------------------------------------------------------------------------
// VectorQuantizerEMA on GB300 — Round 12: 1-term fp16 mma + PACKED top-2
// tracking (u32 key = biased-score bits | 8-bit column tag; 3 IMNMX/score)
// + certified gap test + 8-candidate shortlist rescore.
//   approx_k = zh.eh_k - 0.5|e_k|^2 ; |approx-true| <= |zh| EL + |zl| EM = B
//   margin' = 2B + 0.0625 (mask ulp) + 4e-3 slack.
// ---------------------------------------------------------------------------

#define KCODES 1024
#define DDIM   64
#define NVEC   65536

#define OFF_ZQ    0
#define OFF_LOSS  4194304
#define OFF_IDX   4194305
#define OFF_CS    4259841
#define OFF_EMAW  4260865
#define OFF_EMB   4326401

#define MTILE   128
#define NITEMS  (NVEC / MTILE)       // 512
#define CHUNK   128                  // codes per smem chunk (16 n8-tiles)
#define NCHUNK  (KCODES / CHUNK)     // 8

#define CHUNK_WORDS  4096            // 16 KB per B chunk (eh only)
#define ZSTRIDE 68
// smem float offsets (vq_fused)
#define ZS_OFF     0                 // 8704 floats
#define B_OFF      8704              // 2 x 4096 words
#define SE2_OFF    16896             // 1024
#define SIDX_OFF   17920             // 128 int
#define SCAND_OFF  18048             // 128*8 int
#define SMEM_FLOATS 19072            // 76288 bytes

#define BIAS 2048.0f

// Scratch
__device__ float    g_counts[KCODES];
__device__ float    g_dw[KCODES * DDIM];   // zeroed at END of vq_final
__device__ float    g_e2[KCODES];
__device__ int      g_elm2[2];             // bits of max |el|^2, max |e|^2
__device__ unsigned g_B[NCHUNK * CHUNK_WORDS];   // 128 KB packed half2 (eh)
__device__ float    g_loss;
__device__ int      g_work;

// ---------------------------------------------------------------------------
__device__ __forceinline__ unsigned pack_h2(float a, float b) {
    __half ha = __float2half_rn(a), hb = __float2half_rn(b);
    return (unsigned)__half_as_ushort(ha) |
           ((unsigned)__half_as_ushort(hb) << 16);
}

// ---------------------------------------------------------------------------
// Kernel 0 (proven): zero, |e|^2 EXACT order, norm maxima, fp16 eh B build.
// ---------------------------------------------------------------------------
__global__ __launch_bounds__(256)
void vq_prep(const float* __restrict__ emb) {
    __shared__ float es[128 * 65];
    const int t = threadIdx.x;
    const int b = blockIdx.x;
    const int i = b * 256 + t;                      // 0..32767

    if (i < KCODES) g_counts[i] = 0.0f;
    if (i == 0) { g_loss = 0.0f; g_work = 0; }

    if (b < 8) {
        const float* src = emb + b * 128 * DDIM;
        for (int j = t; j < 128 * DDIM; j += 256) {
            int code = j >> 6, d = j & 63;
            es[code * 65 + d] = src[j];
        }
        __syncthreads();
        if (t < 128) {
            float s = 0.0f, sl = 0.0f;
#pragma unroll
            for (int d = 0; d < DDIM; ++d) {
                float v = es[t * 65 + d];
                s = fmaf(v, v, s);                  // EXACT R6 order
                float hh = __half2float(__float2half_rn(v));
                float l = v - hh;
                sl = fmaf(l, l, sl);
            }
            g_e2[b * 128 + t] = s;
            atomicMax(&g_elm2[0], __float_as_int(sl));
            atomicMax(&g_elm2[1], __float_as_int(s));
        }
    }

    {
        int chunk = i >> 12;
        int rem   = i & 4095;
        int s    = rem >> 8;
        int rem2 = rem & 255;
        int q    = rem2 >> 7;
        int lane = (rem2 >> 2) & 31;
        int j    = rem2 & 3;
        int grp = lane >> 2, tig = lane & 3;
        int w = q * 4 + j;
        int kt = w >> 1, h = w & 1;
        int code = chunk * 128 + s * 8 + grp;
        int d = kt * 16 + tig * 2 + h * 8;
        g_B[i] = pack_h2(emb[code * DDIM + d], emb[code * DDIM + d + 1]);
    }
}

// ---------------------------------------------------------------------------
#define MMAF16(C, A, b0, b1)                                                \
    asm volatile("mma.sync.aligned.m16n8k16.row.col.f32.f16.f16.f32 "       \
                 "{%0,%1,%2,%3}, {%4,%5,%6,%7}, {%8,%9}, {%0,%1,%2,%3};"    \
                 : "+f"(C[0]), "+f"(C[1]), "+f"(C[2]), "+f"(C[3])           \
                 : "r"(A[0]), "r"(A[1]), "r"(A[2]), "r"(A[3]),              \
                   "r"(b0), "r"(b1))

// packed top-2: FADD (bias) + LOP3 (mask|tag) + 3 IMNMX
#define TRACKP(v, metac, bb, ss) do {                                       \
    unsigned _key = (__float_as_uint((v) + BIAS) & 0xFFFFFF00u) | (metac);  \
    unsigned _t = umin(bb, _key);                                           \
    bb = umax(bb, _key);                                                    \
    ss = umax(ss, _t);                                                      \
} while (0)

__device__ __forceinline__ float exact_score(const float* __restrict__ zrow,
                                             const float* __restrict__ se2,
                                             const float* __restrict__ emb,
                                             int k) {
    const float4* ep = (const float4*)(emb + k * DDIM);
    const float4* zp = (const float4*)zrow;
    float acc = 0.0f;
#pragma unroll
    for (int q = 0; q < 16; ++q) {
        float4 e4 = __ldg(&ep[q]);
        float4 zv = zp[q];
        acc = fmaf(zv.x, e4.x, acc);
        acc = fmaf(zv.y, e4.y, acc);
        acc = fmaf(zv.z, e4.z, acc);
        acc = fmaf(zv.w, e4.w, acc);
    }
    return acc - 0.5f * se2[k];
}

// decode packed key -> column index (tag = 255 - (tile<<1|cbit))
__device__ __forceinline__ int key_to_col(unsigned key, int tig) {
    int enc = 255 - (int)(key & 255u);
    return (enc >> 1) * 8 + 2 * tig + (enc & 1);
}

// ---------------------------------------------------------------------------
// Kernel 1: persistent fused 1-term GEMM + packed top-2 cert + epilogue.
// ---------------------------------------------------------------------------
__global__ __launch_bounds__(256, 2)
void vq_fused(const float* __restrict__ z, const float* __restrict__ emb,
              float* __restrict__ out) {
    extern __shared__ float smem[];
    float* zs    = smem + ZS_OFF;
    float* se2   = smem + SE2_OFF;
    int*   sidx  = (int*)(smem + SIDX_OFF);
    int*   scand = (int*)(smem + SCAND_OFF);
    __shared__ int swork;

    const int tid  = threadIdx.x;
    const int wid  = tid >> 5;
    const int lane = tid & 31;
    const int grp  = lane >> 2;
    const int tig  = lane & 3;
    const int row0 = (wid << 4) + grp;        // 0..127 (+8 sibling)
    const unsigned FULL = 0xffffffffu;
    const unsigned GMASK = 0xFu << (grp * 4);

    for (int i = tid; i < KCODES; i += 256) se2[i] = g_e2[i];
    const float EL = sqrtf(__int_as_float(g_elm2[0]));
    const float EM = sqrtf(__int_as_float(g_elm2[1]));
    const unsigned sb  = (unsigned)__cvta_generic_to_shared(smem);
    const unsigned sbB = sb + B_OFF * 4;

    float lacc = 0.0f;

    for (;;) {
        if (tid == 0) swork = atomicAdd(&g_work, 1);
        __syncthreads();
        const int item = swork;
        if (item >= NITEMS) break;

        const int n0  = item * MTILE;
        const int zb  = n0 >> 10;
        const int hw0 = n0 & 1023;
        const float* zsrc = z + (size_t)zb * (DDIM * 1024) + hw0;

        for (int i = tid; i < MTILE * DDIM; i += 256) {
            int d = i >> 7, r = i & 127;
            zs[r * ZSTRIDE + d] = zsrc[d * 1024 + r];
        }
        __syncthreads();

        // ---- A fragments (zh only) + per-row norm bounds ----
        unsigned ah[4][4];
        float zh2_0 = 0.f, zh2_8 = 0.f, zl2_0 = 0.f, zl2_8 = 0.f;
#pragma unroll
        for (int kt = 0; kt < 4; ++kt) {
#pragma unroll
            for (int p = 0; p < 4; ++p) {
                int r = row0 + ((p & 1) << 3);
                int c = kt * 16 + tig * 2 + ((p >> 1) << 3);
                float v0 = zs[r * ZSTRIDE + c];
                float v1 = zs[r * ZSTRIDE + c + 1];
                float h0 = __half2float(__float2half_rn(v0));
                float h1 = __half2float(__float2half_rn(v1));
                ah[kt][p] = pack_h2(v0, v1);
                float l0 = v0 - h0, l1 = v1 - h1;
                if (p & 1) { zh2_8 += h0 * h0 + h1 * h1; zl2_8 += l0 * l0 + l1 * l1; }
                else       { zh2_0 += h0 * h0 + h1 * h1; zl2_0 += l0 * l0 + l1 * l1; }
            }
        }
#pragma unroll
        for (int m = 1; m <= 2; m <<= 1) {
            zh2_0 += __shfl_xor_sync(FULL, zh2_0, m);
            zh2_8 += __shfl_xor_sync(FULL, zh2_8, m);
            zl2_0 += __shfl_xor_sync(FULL, zl2_0, m);
            zl2_8 += __shfl_xor_sync(FULL, zl2_8, m);
        }
        const float margin0 = 2.0f * (sqrtf(zh2_0) * EL + sqrtf(zl2_0) * EM)
                              + 0.0625f + 4e-3f;
        const float margin8 = 2.0f * (sqrtf(zh2_8) * EL + sqrtf(zl2_8) * EM)
                              + 0.0625f + 4e-3f;

        // ---- B chunk 0 ----
        {
            size_t src = __cvta_generic_to_global(g_B);
            for (int i = tid; i < CHUNK_WORDS / 4; i += 256)
                asm volatile("cp.async.ca.shared.global [%0], [%1], 16;"
                             :: "r"(sbB + i * 16), "l"(src + (size_t)i * 16));
            asm volatile("cp.async.commit_group;");
        }

        unsigned bb0 = 0u, ss0 = 0u, bb8 = 0u, ss8 = 0u;   // packed top-2

        for (int ch = 0; ch < NCHUNK; ++ch) {
            if (ch + 1 < NCHUNK) {
                unsigned dst = sbB + ((ch + 1) & 1) * (CHUNK_WORDS * 4);
                size_t   src = __cvta_generic_to_global(g_B) +
                               (size_t)(ch + 1) * CHUNK_WORDS * 4;
                for (int i = tid; i < CHUNK_WORDS / 4; i += 256)
                    asm volatile("cp.async.ca.shared.global [%0], [%1], 16;"
                                 :: "r"(dst + i * 16), "l"(src + (size_t)i * 16));
                asm volatile("cp.async.commit_group;");
                asm volatile("cp.async.wait_group 1;");
            } else {
                asm volatile("cp.async.wait_group 0;");
            }
            __syncthreads();

            const unsigned bufb = sbB + (ch & 1) * (CHUNK_WORDS * 4) + lane * 16;
#pragma unroll 1
            for (int s = 0; s < 16; s += 2) {
                const int nb0 = ch * CHUNK + s * 8;
                const int nb1 = nb0 + 8;
                const unsigned m0 = 255u - (unsigned)((ch * 16 + s) << 1);
                // metas: tile0 c0/c1 = m0, m0-1 ; tile1 c0/c1 = m0-2, m0-3
                float c0[4], c1[4];
                c0[0] = c0[2] = -0.5f * se2[nb0 + 2 * tig];
                c0[1] = c0[3] = -0.5f * se2[nb0 + 2 * tig + 1];
                c1[0] = c1[2] = -0.5f * se2[nb1 + 2 * tig];
                c1[1] = c1[3] = -0.5f * se2[nb1 + 2 * tig + 1];

                unsigned bw0[8], bw1[8];
#pragma unroll
                for (int q = 0; q < 2; ++q) {
                    asm volatile("ld.shared.v4.b32 {%0,%1,%2,%3}, [%4];"
                                 : "=r"(bw0[q * 4]), "=r"(bw0[q * 4 + 1]),
                                   "=r"(bw0[q * 4 + 2]), "=r"(bw0[q * 4 + 3])
                                 : "r"(bufb + (s * 2 + q) * 512));
                    asm volatile("ld.shared.v4.b32 {%0,%1,%2,%3}, [%4];"
                                 : "=r"(bw1[q * 4]), "=r"(bw1[q * 4 + 1]),
                                   "=r"(bw1[q * 4 + 2]), "=r"(bw1[q * 4 + 3])
                                 : "r"(bufb + ((s + 1) * 2 + q) * 512));
                }
#pragma unroll
                for (int kt = 0; kt < 4; ++kt) {
                    MMAF16(c0, ah[kt], bw0[kt * 2], bw0[kt * 2 + 1]);
                    MMAF16(c1, ah[kt], bw1[kt * 2], bw1[kt * 2 + 1]);
                }
                TRACKP(c0[0], m0,     bb0, ss0);
                TRACKP(c0[1], m0 - 1, bb0, ss0);
                TRACKP(c0[2], m0,     bb8, ss8);
                TRACKP(c0[3], m0 - 1, bb8, ss8);
                TRACKP(c1[0], m0 - 2, bb0, ss0);
                TRACKP(c1[1], m0 - 3, bb0, ss0);
                TRACKP(c1[2], m0 - 2, bb8, ss8);
                TRACKP(c1[3], m0 - 3, bb8, ss8);
            }
            __syncthreads();
        }

        // ---- per-lane decode: values (unbias later via compare domain) ----
        float bf0 = __uint_as_float(bb0 & 0xFFFFFF00u);
        float sf0 = __uint_as_float(ss0 & 0xFFFFFF00u);
        float bf8 = __uint_as_float(bb8 & 0xFFFFFF00u);
        float sf8 = __uint_as_float(ss8 & 0xFFFFFF00u);
        int   kb0 = key_to_col(bb0, tig);
        int   ks0 = key_to_col(ss0, tig);
        int   kb8 = key_to_col(bb8, tig);
        int   ks8 = key_to_col(ss8, tig);

        // per-lane candidates (certified shortlist of 8 per row)
        scand[row0 * 8 + tig * 2 + 0]       = kb0;
        scand[row0 * 8 + tig * 2 + 1]       = ks0;
        scand[(row0 + 8) * 8 + tig * 2 + 0] = kb8;
        scand[(row0 + 8) * 8 + tig * 2 + 1] = ks8;
        const float mysec0 = sf0, mysec8 = sf8;     // pre-merge lane 2nds

        // ---- merge top-2 values (+ winner col) across the 4 tig lanes ----
#pragma unroll
        for (int m = 1; m <= 2; m <<= 1) {
            float ob = __shfl_xor_sync(FULL, bf0, m);
            float os = __shfl_xor_sync(FULL, sf0, m);
            int   ok = __shfl_xor_sync(FULL, kb0, m);
            float tm = fminf(bf0, ob);
            if (ob > bf0) kb0 = ok;
            bf0 = fmaxf(bf0, ob);
            sf0 = fmaxf(fmaxf(sf0, os), tm);
            ob = __shfl_xor_sync(FULL, bf8, m);
            os = __shfl_xor_sync(FULL, sf8, m);
            ok = __shfl_xor_sync(FULL, kb8, m);
            tm = fminf(bf8, ob);
            if (ob > bf8) kb8 = ok;
            bf8 = fmaxf(bf8, ob);
            sf8 = fmaxf(fmaxf(sf8, os), tm);
        }
        const float thr0 = bf0 - margin0;
        const float thr8 = bf8 - margin8;
        unsigned d0 = __ballot_sync(FULL, mysec0 >= thr0) & GMASK;
        unsigned d8 = __ballot_sync(FULL, mysec8 >= thr8) & GMASK;
        if (tig == 0) {
            sidx[row0]     = (bf0 - sf0 > margin0) ? kb0 : (d0 ? -2 : -1);
            sidx[row0 + 8] = (bf8 - sf8 > margin8) ? kb8 : (d8 ? -2 : -1);
        }
        __syncwarp();

        // ---- rescore uncertain rows ----
        for (int rr = 0; rr < 16; ++rr) {
            const int r = (wid << 4) + rr;
            const int stat = sidx[r];
            if (stat >= 0) continue;
            int winner;
            if (stat == -1) {
                float mys = -3.4e38f; int myk = 0x7fffffff;
                if (lane < 8) {
                    int k = scand[r * 8 + lane];
                    mys = exact_score(&zs[r * ZSTRIDE], se2, emb, k);
                    myk = k;
                }
#pragma unroll
                for (int off = 16; off; off >>= 1) {
                    float os = __shfl_xor_sync(FULL, mys, off);
                    int   ok = __shfl_xor_sync(FULL, myk, off);
                    if (os > mys || (os == mys && ok < myk)) { mys = os; myk = ok; }
                }
                winner = myk;
            } else {
                float bs = -3.4e38f; int bk = 0x7fffffff;
                for (int k2 = lane; k2 < KCODES; k2 += 32) {
                    float s = exact_score(&zs[r * ZSTRIDE], se2, emb, k2);
                    if (s > bs || (s == bs && k2 < bk)) { bs = s; bk = k2; }
                }
#pragma unroll
                for (int off = 16; off; off >>= 1) {
                    float os = __shfl_xor_sync(FULL, bs, off);
                    int   ok = __shfl_xor_sync(FULL, bk, off);
                    if (os > bs || (os == bs && ok < bk)) { bs = os; bk = ok; }
                }
                winner = bk;
            }
            if (lane == 0) sidx[r] = winner;
        }
        __syncthreads();

        // ---- indices out + counts ----
        if (tid < 128) {
            int w = sidx[tid];
            out[OFF_IDX + n0 + tid] = (float)w;
            atomicAdd(&g_counts[w], 1.0f);
        }

        // ---- fused epilogue (R8-verbatim) ----
        float* zq = out + OFF_ZQ + (size_t)zb * (DDIM * 1024) + hw0;
        const float4* embv = (const float4*)emb;
#pragma unroll 2
        for (int u = tid; u < MTILE * (DDIM / 4); u += 256) {
            int r = u & 127, dg = u >> 7;
            int idx = sidx[r];
            float4 zv = *(const float4*)&zs[r * ZSTRIDE + dg * 4];
            float4 ev = __ldg(&embv[idx * (DDIM / 4) + dg]);
            float d0f = zv.x - ev.x; lacc = fmaf(d0f, d0f, lacc);
            float d1f = zv.y - ev.y; lacc = fmaf(d1f, d1f, lacc);
            float d2f = zv.z - ev.z; lacc = fmaf(d2f, d2f, lacc);
            float d3f = zv.w - ev.w; lacc = fmaf(d3f, d3f, lacc);
            zq[(dg * 4 + 0) * 1024 + r] = zv.x + (ev.x - zv.x);
            zq[(dg * 4 + 1) * 1024 + r] = zv.y + (ev.y - zv.y);
            zq[(dg * 4 + 2) * 1024 + r] = zv.z + (ev.z - zv.z);
            zq[(dg * 4 + 3) * 1024 + r] = zv.w + (ev.w - zv.w);
            asm volatile("red.global.add.v4.f32 [%0], {%1, %2, %3, %4};"
                         :: "l"(&g_dw[idx * DDIM + dg * 4]),
                            "f"(zv.x), "f"(zv.y), "f"(zv.z), "f"(zv.w)
                         : "memory");
        }
    }

#pragma unroll
    for (int o = 16; o > 0; o >>= 1) lacc += __shfl_xor_sync(0xffffffffu, lacc, o);
    if ((tid & 31) == 0) atomicAdd(&g_loss, lacc);
}

// ---------------------------------------------------------------------------
// Kernel 2 (verbatim): merged finalize; re-zeroes g_dw and g_elm2.
// ---------------------------------------------------------------------------
__global__ __launch_bounds__(1024)
void vq_final(const float* __restrict__ cs, const float* __restrict__ ema_w,
              float* __restrict__ out) {
    __shared__ float sncs[1024];
    __shared__ float red[1024];
    int t = threadIdx.x;
    float ncs = fmaf(0.99f, cs[t], 0.01f * g_counts[t]);
    sncs[t] = ncs;
    red[t] = ncs;
    __syncthreads();
#pragma unroll
    for (int s = 512; s > 0; s >>= 1) {
        if (t < s) red[t] += red[t + s];
        __syncthreads();
    }
    float nn = red[0];

    if (blockIdx.x == 0) {
        out[OFF_CS + t] = ncs;
        if (t == 0) out[OFF_LOSS] = 0.25f * g_loss / 4194304.0f;
        if (t < 2) g_elm2[t] = 0;
    }

    int i = blockIdx.x * 1024 + t;
    int k = i >> 6;
    float ne = fmaf(0.99f, ema_w[i], 0.01f * g_dw[i]);
    g_dw[i] = 0.0f;
    out[OFF_EMAW + i] = ne;
    float csv = (sncs[k] + 1e-5f) / (nn + (float)KCODES * 1e-5f) * nn;
    out[OFF_EMB + i] = ne / csv;
}

// ---------------------------------------------------------------------------
extern "C" void kernel_launch(void* const* d_in, const int* in_sizes, int n_in,
                              void* d_out, int out_size) {
    const float* z    = (const float*)d_in[0];
    const float* emb  = (const float*)d_in[1];
    const float* cs   = (const float*)d_in[2];
    const float* emaw = (const float*)d_in[3];
    float* out = (float*)d_out;

    cudaFuncSetAttribute(vq_fused, cudaFuncAttributeMaxDynamicSharedMemorySize,
                         SMEM_FLOATS * 4);

    vq_prep<<<128, 256>>>(emb);
    vq_fused<<<296, 256, SMEM_FLOATS * 4>>>(z, emb, out);
    vq_final<<<64, 1024>>>(cs, emaw, out);
}

// round 13
// speedup vs baseline: 2.1661x; 2.1661x over previous
#include <cuda_runtime.h>
#include <cuda_fp16.h>
#include <cstdint>

// ---------------------------------------------------------------------------
// VectorQuantizerEMA on GB300 — Round 13: 1-term fp16 mma + packed TOP-3
// tracking (u32 key = biased-score bits | 8-bit column tag; 5 IMNMX/score)
// + certified gap test + 12-candidate shortlist rescore.
//   BIAS=256 (mask quantum 0.008), margin = 2B + 0.012;  lane-3rd trigger
//   for the (≈never) full rescore — R11-proven rare, R12-proven-correct keys.
// ---------------------------------------------------------------------------

#define KCODES 1024
#define DDIM   64
#define NVEC   65536

#define OFF_ZQ    0
#define OFF_LOSS  4194304
#define OFF_IDX   4194305
#define OFF_CS    4259841
#define OFF_EMAW  4260865
#define OFF_EMB   4326401

#define MTILE   128
#define NITEMS  (NVEC / MTILE)       // 512
#define CHUNK   128                  // codes per smem chunk (16 n8-tiles)
#define NCHUNK  (KCODES / CHUNK)     // 8

#define CHUNK_WORDS  4096            // 16 KB per B chunk (eh only)
#define ZSTRIDE 68
// smem float offsets (vq_fused)
#define ZS_OFF     0                 // 8704 floats
#define B_OFF      8704              // 2 x 4096 words
#define SE2_OFF    16896             // 1024
#define SIDX_OFF   17920             // 128 int
#define SCAND_OFF  18048             // 128*12 int
#define SMEM_FLOATS 19584            // 78336 bytes

#define BIAS    256.0f
#define MASKPEN 0.012f               // 0.008 mask quantum + 0.004 slack

// Scratch
__device__ float    g_counts[KCODES];
__device__ float    g_dw[KCODES * DDIM];   // zeroed at END of vq_final
__device__ float    g_e2[KCODES];
__device__ int      g_elm2[2];             // bits of max |el|^2, max |e|^2
__device__ unsigned g_B[NCHUNK * CHUNK_WORDS];   // 128 KB packed half2 (eh)
__device__ float    g_loss;
__device__ int      g_work;

// ---------------------------------------------------------------------------
__device__ __forceinline__ unsigned pack_h2(float a, float b) {
    __half ha = __float2half_rn(a), hb = __float2half_rn(b);
    return (unsigned)__half_as_ushort(ha) |
           ((unsigned)__half_as_ushort(hb) << 16);
}

// ---------------------------------------------------------------------------
// Kernel 0 (proven): zero, |e|^2 EXACT order, norm maxima, fp16 eh B build.
// ---------------------------------------------------------------------------
__global__ __launch_bounds__(256)
void vq_prep(const float* __restrict__ emb) {
    __shared__ float es[128 * 65];
    const int t = threadIdx.x;
    const int b = blockIdx.x;
    const int i = b * 256 + t;                      // 0..32767

    if (i < KCODES) g_counts[i] = 0.0f;
    if (i == 0) { g_loss = 0.0f; g_work = 0; }

    if (b < 8) {
        const float* src = emb + b * 128 * DDIM;
        for (int j = t; j < 128 * DDIM; j += 256) {
            int code = j >> 6, d = j & 63;
            es[code * 65 + d] = src[j];
        }
        __syncthreads();
        if (t < 128) {
            float s = 0.0f, sl = 0.0f;
#pragma unroll
            for (int d = 0; d < DDIM; ++d) {
                float v = es[t * 65 + d];
                s = fmaf(v, v, s);                  // EXACT R6 order
                float hh = __half2float(__float2half_rn(v));
                float l = v - hh;
                sl = fmaf(l, l, sl);
            }
            g_e2[b * 128 + t] = s;
            atomicMax(&g_elm2[0], __float_as_int(sl));
            atomicMax(&g_elm2[1], __float_as_int(s));
        }
    }

    {
        int chunk = i >> 12;
        int rem   = i & 4095;
        int s    = rem >> 8;
        int rem2 = rem & 255;
        int q    = rem2 >> 7;
        int lane = (rem2 >> 2) & 31;
        int j    = rem2 & 3;
        int grp = lane >> 2, tig = lane & 3;
        int w = q * 4 + j;
        int kt = w >> 1, h = w & 1;
        int code = chunk * 128 + s * 8 + grp;
        int d = kt * 16 + tig * 2 + h * 8;
        g_B[i] = pack_h2(emb[code * DDIM + d], emb[code * DDIM + d + 1]);
    }
}

// ---------------------------------------------------------------------------
#define MMAF16(C, A, b0, b1)                                                \
    asm volatile("mma.sync.aligned.m16n8k16.row.col.f32.f16.f16.f32 "       \
                 "{%0,%1,%2,%3}, {%4,%5,%6,%7}, {%8,%9}, {%0,%1,%2,%3};"    \
                 : "+f"(C[0]), "+f"(C[1]), "+f"(C[2]), "+f"(C[3])           \
                 : "r"(A[0]), "r"(A[1]), "r"(A[2]), "r"(A[3]),              \
                   "r"(b0), "r"(b1))

// packed top-3: FADD (bias) + LOP3 (mask|tag) + 5 IMNMX
#define TRACKP3(v, metac, bb, s2, b3) do {                                  \
    unsigned _key = (__float_as_uint((v) + BIAS) & 0xFFFFFF00u) | (metac);  \
    unsigned _t1 = umin(bb, _key);                                          \
    bb = umax(bb, _key);                                                    \
    unsigned _t2 = umin(s2, _t1);                                           \
    s2 = umax(s2, _t1);                                                     \
    b3 = umax(b3, _t2);                                                     \
} while (0)

__device__ __forceinline__ float exact_score(const float* __restrict__ zrow,
                                             const float* __restrict__ se2,
                                             const float* __restrict__ emb,
                                             int k) {
    const float4* ep = (const float4*)(emb + k * DDIM);
    const float4* zp = (const float4*)zrow;
    float acc = 0.0f;
#pragma unroll
    for (int q = 0; q < 16; ++q) {
        float4 e4 = __ldg(&ep[q]);
        float4 zv = zp[q];
        acc = fmaf(zv.x, e4.x, acc);
        acc = fmaf(zv.y, e4.y, acc);
        acc = fmaf(zv.z, e4.z, acc);
        acc = fmaf(zv.w, e4.w, acc);
    }
    return acc - 0.5f * se2[k];
}

// decode packed key -> column index (tag = 255 - (tile<<1|cbit))
__device__ __forceinline__ int key_to_col(unsigned key, int tig) {
    int enc = 255 - (int)(key & 255u);
    return (enc >> 1) * 8 + 2 * tig + (enc & 1);
}

// ---------------------------------------------------------------------------
// Kernel 1: persistent fused 1-term GEMM + packed top-3 cert + epilogue.
// ---------------------------------------------------------------------------
__global__ __launch_bounds__(256, 2)
void vq_fused(const float* __restrict__ z, const float* __restrict__ emb,
              float* __restrict__ out) {
    extern __shared__ float smem[];
    float* zs    = smem + ZS_OFF;
    float* se2   = smem + SE2_OFF;
    int*   sidx  = (int*)(smem + SIDX_OFF);
    int*   scand = (int*)(smem + SCAND_OFF);
    __shared__ int swork;

    const int tid  = threadIdx.x;
    const int wid  = tid >> 5;
    const int lane = tid & 31;
    const int grp  = lane >> 2;
    const int tig  = lane & 3;
    const int row0 = (wid << 4) + grp;        // 0..127 (+8 sibling)
    const unsigned FULL = 0xffffffffu;
    const unsigned GMASK = 0xFu << (grp * 4);

    for (int i = tid; i < KCODES; i += 256) se2[i] = g_e2[i];
    const float EL = sqrtf(__int_as_float(g_elm2[0]));
    const float EM = sqrtf(__int_as_float(g_elm2[1]));
    const unsigned sb  = (unsigned)__cvta_generic_to_shared(smem);
    const unsigned sbB = sb + B_OFF * 4;

    float lacc = 0.0f;

    for (;;) {
        if (tid == 0) swork = atomicAdd(&g_work, 1);
        __syncthreads();
        const int item = swork;
        if (item >= NITEMS) break;

        const int n0  = item * MTILE;
        const int zb  = n0 >> 10;
        const int hw0 = n0 & 1023;
        const float* zsrc = z + (size_t)zb * (DDIM * 1024) + hw0;

        for (int i = tid; i < MTILE * DDIM; i += 256) {
            int d = i >> 7, r = i & 127;
            zs[r * ZSTRIDE + d] = zsrc[d * 1024 + r];
        }
        __syncthreads();

        // ---- A fragments (zh only) + per-row norm bounds ----
        unsigned ah[4][4];
        float zh2_0 = 0.f, zh2_8 = 0.f, zl2_0 = 0.f, zl2_8 = 0.f;
#pragma unroll
        for (int kt = 0; kt < 4; ++kt) {
#pragma unroll
            for (int p = 0; p < 4; ++p) {
                int r = row0 + ((p & 1) << 3);
                int c = kt * 16 + tig * 2 + ((p >> 1) << 3);
                float v0 = zs[r * ZSTRIDE + c];
                float v1 = zs[r * ZSTRIDE + c + 1];
                float h0 = __half2float(__float2half_rn(v0));
                float h1 = __half2float(__float2half_rn(v1));
                ah[kt][p] = pack_h2(v0, v1);
                float l0 = v0 - h0, l1 = v1 - h1;
                if (p & 1) { zh2_8 += h0 * h0 + h1 * h1; zl2_8 += l0 * l0 + l1 * l1; }
                else       { zh2_0 += h0 * h0 + h1 * h1; zl2_0 += l0 * l0 + l1 * l1; }
            }
        }
#pragma unroll
        for (int m = 1; m <= 2; m <<= 1) {
            zh2_0 += __shfl_xor_sync(FULL, zh2_0, m);
            zh2_8 += __shfl_xor_sync(FULL, zh2_8, m);
            zl2_0 += __shfl_xor_sync(FULL, zl2_0, m);
            zl2_8 += __shfl_xor_sync(FULL, zl2_8, m);
        }
        const float margin0 = 2.0f * (sqrtf(zh2_0) * EL + sqrtf(zl2_0) * EM) + MASKPEN;
        const float margin8 = 2.0f * (sqrtf(zh2_8) * EL + sqrtf(zl2_8) * EM) + MASKPEN;

        // ---- B chunk 0 ----
        {
            size_t src = __cvta_generic_to_global(g_B);
            for (int i = tid; i < CHUNK_WORDS / 4; i += 256)
                asm volatile("cp.async.ca.shared.global [%0], [%1], 16;"
                             :: "r"(sbB + i * 16), "l"(src + (size_t)i * 16));
            asm volatile("cp.async.commit_group;");
        }

        unsigned bb0 = 0u, s20 = 0u, b30 = 0u;     // packed top-3 (row0)
        unsigned bb8 = 0u, s28 = 0u, b38 = 0u;     // packed top-3 (row0+8)

        for (int ch = 0; ch < NCHUNK; ++ch) {
            if (ch + 1 < NCHUNK) {
                unsigned dst = sbB + ((ch + 1) & 1) * (CHUNK_WORDS * 4);
                size_t   src = __cvta_generic_to_global(g_B) +
                               (size_t)(ch + 1) * CHUNK_WORDS * 4;
                for (int i = tid; i < CHUNK_WORDS / 4; i += 256)
                    asm volatile("cp.async.ca.shared.global [%0], [%1], 16;"
                                 :: "r"(dst + i * 16), "l"(src + (size_t)i * 16));
                asm volatile("cp.async.commit_group;");
                asm volatile("cp.async.wait_group 1;");
            } else {
                asm volatile("cp.async.wait_group 0;");
            }
            __syncthreads();

            const unsigned bufb = sbB + (ch & 1) * (CHUNK_WORDS * 4) + lane * 16;
#pragma unroll 1
            for (int s = 0; s < 16; s += 2) {
                const int nb0 = ch * CHUNK + s * 8;
                const int nb1 = nb0 + 8;
                const unsigned m0 = 255u - (unsigned)((ch * 16 + s) << 1);
                float c0[4], c1[4];
                c0[0] = c0[2] = -0.5f * se2[nb0 + 2 * tig];
                c0[1] = c0[3] = -0.5f * se2[nb0 + 2 * tig + 1];
                c1[0] = c1[2] = -0.5f * se2[nb1 + 2 * tig];
                c1[1] = c1[3] = -0.5f * se2[nb1 + 2 * tig + 1];

                unsigned bw0[8], bw1[8];
#pragma unroll
                for (int q = 0; q < 2; ++q) {
                    asm volatile("ld.shared.v4.b32 {%0,%1,%2,%3}, [%4];"
                                 : "=r"(bw0[q * 4]), "=r"(bw0[q * 4 + 1]),
                                   "=r"(bw0[q * 4 + 2]), "=r"(bw0[q * 4 + 3])
                                 : "r"(bufb + (s * 2 + q) * 512));
                    asm volatile("ld.shared.v4.b32 {%0,%1,%2,%3}, [%4];"
                                 : "=r"(bw1[q * 4]), "=r"(bw1[q * 4 + 1]),
                                   "=r"(bw1[q * 4 + 2]), "=r"(bw1[q * 4 + 3])
                                 : "r"(bufb + ((s + 1) * 2 + q) * 512));
                }
#pragma unroll
                for (int kt = 0; kt < 4; ++kt) {
                    MMAF16(c0, ah[kt], bw0[kt * 2], bw0[kt * 2 + 1]);
                    MMAF16(c1, ah[kt], bw1[kt * 2], bw1[kt * 2 + 1]);
                }
                TRACKP3(c0[0], m0,     bb0, s20, b30);
                TRACKP3(c0[1], m0 - 1, bb0, s20, b30);
                TRACKP3(c0[2], m0,     bb8, s28, b38);
                TRACKP3(c0[3], m0 - 1, bb8, s28, b38);
                TRACKP3(c1[0], m0 - 2, bb0, s20, b30);
                TRACKP3(c1[1], m0 - 3, bb0, s20, b30);
                TRACKP3(c1[2], m0 - 2, bb8, s28, b38);
                TRACKP3(c1[3], m0 - 3, bb8, s28, b38);
            }
            __syncthreads();
        }

        // ---- per-lane decode (biased-masked float domain; bias cancels in
        //      all gap comparisons) ----
        float bf0 = __uint_as_float(bb0 & 0xFFFFFF00u);
        float sf0 = __uint_as_float(s20 & 0xFFFFFF00u);
        float tf0 = __uint_as_float(b30 & 0xFFFFFF00u);
        float bf8 = __uint_as_float(bb8 & 0xFFFFFF00u);
        float sf8 = __uint_as_float(s28 & 0xFFFFFF00u);
        float tf8 = __uint_as_float(b38 & 0xFFFFFF00u);
        int   kb0 = key_to_col(bb0, tig);
        int   kb8 = key_to_col(bb8, tig);

        // per-lane candidates (certified shortlist of 12 per row)
        scand[row0 * 12 + tig * 3 + 0] = kb0;
        scand[row0 * 12 + tig * 3 + 1] = key_to_col(s20, tig);
        scand[row0 * 12 + tig * 3 + 2] = key_to_col(b30, tig);
        scand[(row0 + 8) * 12 + tig * 3 + 0] = kb8;
        scand[(row0 + 8) * 12 + tig * 3 + 1] = key_to_col(s28, tig);
        scand[(row0 + 8) * 12 + tig * 3 + 2] = key_to_col(b38, tig);

        // ---- merge top-2 values (+ winner col) across the 4 tig lanes ----
#pragma unroll
        for (int m = 1; m <= 2; m <<= 1) {
            float ob = __shfl_xor_sync(FULL, bf0, m);
            float os = __shfl_xor_sync(FULL, sf0, m);
            int   ok = __shfl_xor_sync(FULL, kb0, m);
            float tm = fminf(bf0, ob);
            if (ob > bf0) kb0 = ok;
            bf0 = fmaxf(bf0, ob);
            sf0 = fmaxf(fmaxf(sf0, os), tm);
            ob = __shfl_xor_sync(FULL, bf8, m);
            os = __shfl_xor_sync(FULL, sf8, m);
            ok = __shfl_xor_sync(FULL, kb8, m);
            tm = fminf(bf8, ob);
            if (ob > bf8) kb8 = ok;
            bf8 = fmaxf(bf8, ob);
            sf8 = fmaxf(fmaxf(sf8, os), tm);
        }
        const float thr0 = bf0 - margin0;
        const float thr8 = bf8 - margin8;
        // doubly-uncertain: some lane's 3rd above threshold (≈never)
        unsigned d0 = __ballot_sync(FULL, tf0 >= thr0) & GMASK;
        unsigned d8 = __ballot_sync(FULL, tf8 >= thr8) & GMASK;
        if (tig == 0) {
            sidx[row0]     = (bf0 - sf0 > margin0) ? kb0 : (d0 ? -2 : -1);
            sidx[row0 + 8] = (bf8 - sf8 > margin8) ? kb8 : (d8 ? -2 : -1);
        }
        __syncwarp();

        // ---- rescore uncertain rows ----
        for (int rr = 0; rr < 16; ++rr) {
            const int r = (wid << 4) + rr;
            const int stat = sidx[r];
            if (stat >= 0) continue;
            int winner;
            if (stat == -1) {
                float mys = -3.4e38f; int myk = 0x7fffffff;
                if (lane < 12) {
                    int k = scand[r * 12 + lane];
                    mys = exact_score(&zs[r * ZSTRIDE], se2, emb, k);
                    myk = k;
                }
#pragma unroll
                for (int off = 16; off; off >>= 1) {
                    float os = __shfl_xor_sync(FULL, mys, off);
                    int   ok = __shfl_xor_sync(FULL, myk, off);
                    if (os > mys || (os == mys && ok < myk)) { mys = os; myk = ok; }
                }
                winner = myk;
            } else {
                float bs = -3.4e38f; int bk = 0x7fffffff;
                for (int k2 = lane; k2 < KCODES; k2 += 32) {
                    float s = exact_score(&zs[r * ZSTRIDE], se2, emb, k2);
                    if (s > bs || (s == bs && k2 < bk)) { bs = s; bk = k2; }
                }
#pragma unroll
                for (int off = 16; off; off >>= 1) {
                    float os = __shfl_xor_sync(FULL, bs, off);
                    int   ok = __shfl_xor_sync(FULL, bk, off);
                    if (os > bs || (os == bs && ok < bk)) { bs = os; bk = ok; }
                }
                winner = bk;
            }
            if (lane == 0) sidx[r] = winner;
        }
        __syncthreads();

        // ---- indices out + counts ----
        if (tid < 128) {
            int w = sidx[tid];
            out[OFF_IDX + n0 + tid] = (float)w;
            atomicAdd(&g_counts[w], 1.0f);
        }

        // ---- fused epilogue (R8-verbatim) ----
        float* zq = out + OFF_ZQ + (size_t)zb * (DDIM * 1024) + hw0;
        const float4* embv = (const float4*)emb;
#pragma unroll 2
        for (int u = tid; u < MTILE * (DDIM / 4); u += 256) {
            int r = u & 127, dg = u >> 7;
            int idx = sidx[r];
            float4 zv = *(const float4*)&zs[r * ZSTRIDE + dg * 4];
            float4 ev = __ldg(&embv[idx * (DDIM / 4) + dg]);
            float d0f = zv.x - ev.x; lacc = fmaf(d0f, d0f, lacc);
            float d1f = zv.y - ev.y; lacc = fmaf(d1f, d1f, lacc);
            float d2f = zv.z - ev.z; lacc = fmaf(d2f, d2f, lacc);
            float d3f = zv.w - ev.w; lacc = fmaf(d3f, d3f, lacc);
            zq[(dg * 4 + 0) * 1024 + r] = zv.x + (ev.x - zv.x);
            zq[(dg * 4 + 1) * 1024 + r] = zv.y + (ev.y - zv.y);
            zq[(dg * 4 + 2) * 1024 + r] = zv.z + (ev.z - zv.z);
            zq[(dg * 4 + 3) * 1024 + r] = zv.w + (ev.w - zv.w);
            asm volatile("red.global.add.v4.f32 [%0], {%1, %2, %3, %4};"
                         :: "l"(&g_dw[idx * DDIM + dg * 4]),
                            "f"(zv.x), "f"(zv.y), "f"(zv.z), "f"(zv.w)
                         : "memory");
        }
    }

#pragma unroll
    for (int o = 16; o > 0; o >>= 1) lacc += __shfl_xor_sync(0xffffffffu, lacc, o);
    if ((tid & 31) == 0) atomicAdd(&g_loss, lacc);
}

// ---------------------------------------------------------------------------
// Kernel 2 (verbatim): merged finalize; re-zeroes g_dw and g_elm2.
// ---------------------------------------------------------------------------
__global__ __launch_bounds__(1024)
void vq_final(const float* __restrict__ cs, const float* __restrict__ ema_w,
              float* __restrict__ out) {
    __shared__ float sncs[1024];
    __shared__ float red[1024];
    int t = threadIdx.x;
    float ncs = fmaf(0.99f, cs[t], 0.01f * g_counts[t]);
    sncs[t] = ncs;
    red[t] = ncs;
    __syncthreads();
#pragma unroll
    for (int s = 512; s > 0; s >>= 1) {
        if (t < s) red[t] += red[t + s];
        __syncthreads();
    }
    float nn = red[0];

    if (blockIdx.x == 0) {
        out[OFF_CS + t] = ncs;
        if (t == 0) out[OFF_LOSS] = 0.25f * g_loss / 4194304.0f;
        if (t < 2) g_elm2[t] = 0;
    }

    int i = blockIdx.x * 1024 + t;
    int k = i >> 6;
    float ne = fmaf(0.99f, ema_w[i], 0.01f * g_dw[i]);
    g_dw[i] = 0.0f;
    out[OFF_EMAW + i] = ne;
    float csv = (sncs[k] + 1e-5f) / (nn + (float)KCODES * 1e-5f) * nn;
    out[OFF_EMB + i] = ne / csv;
}

// ---------------------------------------------------------------------------
extern "C" void kernel_launch(void* const* d_in, const int* in_sizes, int n_in,
                              void* d_out, int out_size) {
    const float* z    = (const float*)d_in[0];
    const float* emb  = (const float*)d_in[1];
    const float* cs   = (const float*)d_in[2];
    const float* emaw = (const float*)d_in[3];
    float* out = (float*)d_out;

    cudaFuncSetAttribute(vq_fused, cudaFuncAttributeMaxDynamicSharedMemorySize,
                         SMEM_FLOATS * 4);

    vq_prep<<<128, 256>>>(emb);
    vq_fused<<<296, 256, SMEM_FLOATS * 4>>>(z, emb, out);
    vq_final<<<64, 1024>>>(cs, emaw, out);
}